// round 11
// baseline (speedup 1.0000x reference)
#include <cuda_runtime.h>
#include <cuda_bf16.h>
#include <cstdint>
#include <math.h>

#define NT      262144      // total nodes (512 subgraphs x 512 nodes)
#define NN      512         // nodes per subgraph / original graph
#define E_SUB   2097152     // edges in union-of-subgraphs graph
#define EO      8192        // edges in original graph
#define D       64          // emb dim
#define LAYERS  4

// ---- mma tile smem layout (word == uint32 == 2 bf16) ----
#define AP      36                      // word pitch for A rows (conflict-free)
#define AW_WORDS (128 * AP)             // 4608 words per A sub-tile
#define WW_WORDS (64 * AP)              // 2304 words per W sub-tile
#define SMO_BIAS ((4 * AW_WORDS + 4 * WW_WORDS) * 4)   // 110592
#define SM_MMA_BYTES (SMO_BIAS + 256)                  // 110848

// ------------------------- device scratch (no cudaMalloc allowed) ----------
__device__ __align__(16) float g_hA[(size_t)NT * D];
__device__ __align__(16) float g_hB[(size_t)NT * D];
__device__ __align__(16) float g_Y[(size_t)NT * D];

__device__ __align__(16) float g_xsum[NN * D];
__device__ __align__(16) float g_aggs[NN * D];
__device__ __align__(16) float g_y2[NN * D];
__device__ __align__(16) float g_add2[NN * D];   // y2*scale_s + shift_s + shift

__device__ __align__(16) float g_stA[2 * D];
__device__ __align__(16) float g_stS[2 * D];
__device__ __align__(16) float g_scale[D],  g_shift[D];
__device__ __align__(16) float g_scale_s[D], g_shift_s[D];

__device__ int g_cnt[NT];
__device__ int g_rowptr[NT + 1];
__device__ int g_bsum[256];
__device__ int g_csrsrc[E_SUB];

// ------------------------- CSR build ---------------------------------------
__global__ void k_hist(const int* __restrict__ dst) {
    int e = blockIdx.x * blockDim.x + threadIdx.x;
    if (e < E_SUB) atomicAdd(&g_cnt[dst[e]], 1);
}

__global__ void k_bsum() {
    __shared__ int sh[256];
    int b = blockIdx.x, t = threadIdx.x;
    int base = b * 1024 + t * 4;
    int v = g_cnt[base] + g_cnt[base + 1] + g_cnt[base + 2] + g_cnt[base + 3];
    sh[t] = v;
    __syncthreads();
    for (int off = 128; off > 0; off >>= 1) {
        if (t < off) sh[t] += sh[t + off];
        __syncthreads();
    }
    if (t == 0) g_bsum[b] = sh[0];
}

__global__ void k_scanb() {
    __shared__ int sh[256];
    int t = threadIdx.x;
    int orig = g_bsum[t];
    sh[t] = orig;
    __syncthreads();
    for (int off = 1; off < 256; off <<= 1) {
        int v = (t >= off) ? sh[t - off] : 0;
        __syncthreads();
        sh[t] += v;
        __syncthreads();
    }
    g_bsum[t] = sh[t] - orig;   // exclusive
}

__global__ void k_scanlocal() {
    __shared__ int sh[256];
    int b = blockIdx.x, t = threadIdx.x;
    int base = (b * 256 + t) * 4;
    int c0 = g_cnt[base], c1 = g_cnt[base + 1], c2 = g_cnt[base + 2], c3 = g_cnt[base + 3];
    int tsum = c0 + c1 + c2 + c3;
    sh[t] = tsum;
    __syncthreads();
    for (int off = 1; off < 256; off <<= 1) {
        int v = (t >= off) ? sh[t - off] : 0;
        __syncthreads();
        sh[t] += v;
        __syncthreads();
    }
    int excl = sh[t] - tsum + g_bsum[b];
    int e0 = excl, e1 = e0 + c0, e2 = e1 + c1, e3 = e2 + c2;
    g_rowptr[base] = e0; g_rowptr[base + 1] = e1;
    g_rowptr[base + 2] = e2; g_rowptr[base + 3] = e3;
    g_cnt[base] = e0; g_cnt[base + 1] = e1;
    g_cnt[base + 2] = e2; g_cnt[base + 3] = e3;
    if (b == 255 && t == 255) g_rowptr[NT] = E_SUB;
}

__global__ void k_scatter(const int* __restrict__ src, const int* __restrict__ dst) {
    int e = blockIdx.x * blockDim.x + threadIdx.x;
    if (e < E_SUB) {
        int pos = atomicAdd(&g_cnt[dst[e]], 1);
        g_csrsrc[pos] = src[e];
    }
}

// ---------------- bf16 split helpers ----------------------------------------
__device__ __forceinline__ void split2(float x, float y, uint32_t& hi, uint32_t& lo) {
    __nv_bfloat16 hx = __float2bfloat16_rn(x);
    __nv_bfloat16 hy = __float2bfloat16_rn(y);
    __nv_bfloat162 hp = __halves2bfloat162(hx, hy);          // low half = x
    hi = *reinterpret_cast<uint32_t*>(&hp);
    __nv_bfloat162 lp = __floats2bfloat162_rn(
        x - __bfloat162float(hx), y - __bfloat162float(hy));
    lo = *reinterpret_cast<uint32_t*>(&lp);
}

__device__ __forceinline__ void mma_bf16(float* c, uint32_t a0, uint32_t a1,
                                         uint32_t a2, uint32_t a3,
                                         uint32_t b0, uint32_t b1) {
    asm volatile(
        "mma.sync.aligned.m16n8k16.row.col.f32.bf16.bf16.f32 "
        "{%0,%1,%2,%3}, {%4,%5,%6,%7}, {%8,%9}, {%0,%1,%2,%3};"
        : "+f"(c[0]), "+f"(c[1]), "+f"(c[2]), "+f"(c[3])
        : "r"(a0), "r"(a1), "r"(a2), "r"(a3), "r"(b0), "r"(b1));
}

// -------- fused gather + dual GEMM on tensor cores (mma.sync bf16 split) ----
// A0[r] = sum_{src in row r} h[src]   (gathered in-kernel, fp32)
// A1[r] = h[r]
// Y[r][c] = A0[r]@W0[c] + A1[r]@W1[c] + bias[c];  fused BN stats.
__global__ void __launch_bounds__(256, 2)
k_gemm_mma(const float* __restrict__ h,
           const float* __restrict__ W0, const float* __restrict__ W1v,
           const float* __restrict__ bias, float* __restrict__ Y,
           float* __restrict__ st) {
    extern __shared__ char smem[];
    uint32_t* Aw = reinterpret_cast<uint32_t*>(smem);             // Ah0 Al0 Ah1 Al1
    uint32_t* Ww = Aw + 4 * AW_WORDS;                             // Wh0 Wl0 Wh1 Wl1
    float* bias_s = reinterpret_cast<float*>(smem + SMO_BIAS);

    int t = threadIdx.x;
    int w = t >> 5, lane = t & 31;
    int g = lane >> 2, tg = lane & 3;
    int row0 = blockIdx.x * 128;

    if (t < 64) bias_s[t] = bias[t];

    // ---- W tiles: 64x64 fp32 -> bf16 hi/lo ----
    for (int p = 0; p < 2; p++) {
        const float4* src = reinterpret_cast<const float4*>(p ? W1v : W0);
        uint32_t* hb = Ww + (2 * p) * WW_WORDS;
        uint32_t* lb = hb + WW_WORDS;
#pragma unroll
        for (int it = 0; it < 4; it++) {
            int task = it * 256 + t;        // 1024 tasks = 64 rows x 16 float4
            int r = task >> 4, f = task & 15;
            float4 v = src[r * 16 + f];
            uint32_t h0, l0, h1, l1;
            split2(v.x, v.y, h0, l0);
            split2(v.z, v.w, h1, l1);
            hb[r * AP + 2 * f]     = h0;
            hb[r * AP + 2 * f + 1] = h1;
            lb[r * AP + 2 * f]     = l0;
            lb[r * AP + 2 * f + 1] = l1;
        }
    }

    // ---- fused gather + A-tile conversion: warp w owns rows w*16..w*16+15 --
    {
        uint32_t* Ah0 = Aw;
        uint32_t* Al0 = Aw + AW_WORDS;
        uint32_t* Ah1 = Aw + 2 * AW_WORDS;
        uint32_t* Al1 = Aw + 3 * AW_WORDS;
        const float2* h2 = reinterpret_cast<const float2*>(h);
#pragma unroll 1
        for (int rr = 0; rr < 16; rr++) {
            int lr = w * 16 + rr;
            int gr = row0 + lr;
            float2 hv = h2[(size_t)gr * 32 + lane];        // A1 row (independent)
            int s = g_rowptr[gr], e = g_rowptr[gr + 1];
            float2 a = make_float2(0.f, 0.f), b = make_float2(0.f, 0.f);
            float2 c = make_float2(0.f, 0.f), d = make_float2(0.f, 0.f);
            int i = s;
            for (; i + 3 < e; i += 4) {
                int s0 = g_csrsrc[i],     s1 = g_csrsrc[i + 1];
                int s2 = g_csrsrc[i + 2], s3 = g_csrsrc[i + 3];
                float2 v0 = h2[(size_t)s0 * 32 + lane];
                float2 v1 = h2[(size_t)s1 * 32 + lane];
                float2 v2 = h2[(size_t)s2 * 32 + lane];
                float2 v3 = h2[(size_t)s3 * 32 + lane];
                a.x += v0.x; a.y += v0.y;
                b.x += v1.x; b.y += v1.y;
                c.x += v2.x; c.y += v2.y;
                d.x += v3.x; d.y += v3.y;
            }
            for (; i < e; i++) {
                int s0 = g_csrsrc[i];
                float2 v0 = h2[(size_t)s0 * 32 + lane];
                a.x += v0.x; a.y += v0.y;
            }
            float2 sum = make_float2(a.x + b.x + c.x + d.x,
                                     a.y + b.y + c.y + d.y);
            uint32_t hiw, low;
            split2(sum.x, sum.y, hiw, low);
            Ah0[lr * AP + lane] = hiw;
            Al0[lr * AP + lane] = low;
            split2(hv.x, hv.y, hiw, low);
            Ah1[lr * AP + lane] = hiw;
            Al1[lr * AP + lane] = low;
        }
    }
    __syncthreads();

    // ---- warp tile: 16 rows x 64 cols; acc[j] = m16n8 fragment ----
    float acc[8][4];
#pragma unroll
    for (int j = 0; j < 8; j++)
#pragma unroll
        for (int i = 0; i < 4; i++) acc[j][i] = 0.f;

    int ra = (w * 16 + g) * AP;
    int rb = (w * 16 + g + 8) * AP;

#pragma unroll
    for (int p = 0; p < 2; p++) {
        const uint32_t* Ah_ = Aw + (2 * p) * AW_WORDS;
        const uint32_t* Al_ = Ah_ + AW_WORDS;
        const uint32_t* Wh_ = Ww + (2 * p) * WW_WORDS;
        const uint32_t* Wl_ = Wh_ + WW_WORDS;
#pragma unroll
        for (int ks = 0; ks < 4; ks++) {
            int o = ks * 8 + tg;
            uint32_t ah0 = Ah_[ra + o],     ah1 = Ah_[rb + o];
            uint32_t ah2 = Ah_[ra + o + 4], ah3 = Ah_[rb + o + 4];
            uint32_t al0 = Al_[ra + o],     al1 = Al_[rb + o];
            uint32_t al2 = Al_[ra + o + 4], al3 = Al_[rb + o + 4];
#pragma unroll
            for (int j = 0; j < 8; j++) {
                int wb = (j * 8 + g) * AP + o;
                uint32_t bh0 = Wh_[wb], bh1 = Wh_[wb + 4];
                uint32_t bl0 = Wl_[wb], bl1 = Wl_[wb + 4];
                mma_bf16(acc[j], ah0, ah1, ah2, ah3, bh0, bh1);
                mma_bf16(acc[j], al0, al1, al2, al3, bh0, bh1);
                mma_bf16(acc[j], ah0, ah1, ah2, ah3, bl0, bl1);
            }
        }
    }

    // ---- epilogue: bias, write Y, BN stat partials ----
    float ps0[8], ps1[8], pq0[8], pq1[8];
    int r0g = row0 + w * 16 + g;
#pragma unroll
    for (int j = 0; j < 8; j++) {
        int c0 = j * 8 + 2 * tg;
        float b0 = bias_s[c0], b1 = bias_s[c0 + 1];
        float y00 = acc[j][0] + b0, y01 = acc[j][1] + b1;
        float y10 = acc[j][2] + b0, y11 = acc[j][3] + b1;
        *reinterpret_cast<float2*>(&Y[(size_t)r0g * D + c0]) = make_float2(y00, y01);
        *reinterpret_cast<float2*>(&Y[(size_t)(r0g + 8) * D + c0]) = make_float2(y10, y11);
        ps0[j] = y00 + y10; ps1[j] = y01 + y11;
        pq0[j] = y00 * y00 + y10 * y10;
        pq1[j] = y01 * y01 + y11 * y11;
    }

    __syncthreads();                                  // smem A/W now free
    float* redS = reinterpret_cast<float*>(smem);     // [64][72]
    float* redQ = redS + 64 * 72;
    int grp = w * 8 + g;
#pragma unroll
    for (int j = 0; j < 8; j++) {
        int c0 = j * 8 + 2 * tg;
        *reinterpret_cast<float2*>(&redS[grp * 72 + c0]) = make_float2(ps0[j], ps1[j]);
        *reinterpret_cast<float2*>(&redQ[grp * 72 + c0]) = make_float2(pq0[j], pq1[j]);
    }
    __syncthreads();
    if (t < 64) {
        float s = 0.f, q = 0.f;
#pragma unroll 4
        for (int k = 0; k < 64; k++) {
            s += redS[k * 72 + t];
            q += redQ[k * 72 + t];
        }
        atomicAdd(&st[t], s);
        atomicAdd(&st[64 + t], q);
    }
}

// ------------------------- small dual GEMM (scalar, fused stats) ------------
__global__ void __launch_bounds__(256)
k_gemmR(const float* __restrict__ A0, const float* __restrict__ A1,
        const float* __restrict__ W0, const float* __restrict__ W1v,
        const float* __restrict__ bias, float* __restrict__ Y,
        float* __restrict__ st) {
    __shared__ __align__(16) float sA[64][65];
    __shared__ __align__(16) float sW[64][68];
    int t  = threadIdx.x;
    int tx = t & 15, ty = t >> 4;
    int row0 = blockIdx.x * 64;
    int cc = t & 63, rb = t >> 6;

    float acc[4][4];
#pragma unroll
    for (int i = 0; i < 4; i++)
#pragma unroll
        for (int j = 0; j < 4; j++) acc[i][j] = 0.f;

    for (int p = 0; p < 2; p++) {
        const float* A = p ? A1 : A0;
        const float* W = p ? W1v : W0;
#pragma unroll
        for (int j = 0; j < 16; j++) {
            int r = rb + j * 4;
            sA[cc][r] = A[(size_t)(row0 + r) * D + cc];
        }
#pragma unroll
        for (int j = 0; j < 16; j++) {
            int ci = rb + j * 4;
            sW[cc][ci] = W[ci * D + cc];
        }
        __syncthreads();
#pragma unroll
        for (int k = 0; k < 64; k++) {
            float4 bv = *reinterpret_cast<const float4*>(&sW[k][tx * 4]);
            float a0 = sA[k][ty * 4 + 0];
            float a1 = sA[k][ty * 4 + 1];
            float a2 = sA[k][ty * 4 + 2];
            float a3 = sA[k][ty * 4 + 3];
            acc[0][0] += a0 * bv.x; acc[0][1] += a0 * bv.y; acc[0][2] += a0 * bv.z; acc[0][3] += a0 * bv.w;
            acc[1][0] += a1 * bv.x; acc[1][1] += a1 * bv.y; acc[1][2] += a1 * bv.z; acc[1][3] += a1 * bv.w;
            acc[2][0] += a2 * bv.x; acc[2][1] += a2 * bv.y; acc[2][2] += a2 * bv.z; acc[2][3] += a2 * bv.w;
            acc[3][0] += a3 * bv.x; acc[3][1] += a3 * bv.y; acc[3][2] += a3 * bv.z; acc[3][3] += a3 * bv.w;
        }
        __syncthreads();
    }

    float4 bb = *reinterpret_cast<const float4*>(&bias[tx * 4]);
    float bcol[4] = { bb.x, bb.y, bb.z, bb.w };
    float ls[4] = {0.f, 0.f, 0.f, 0.f};
    float lq[4] = {0.f, 0.f, 0.f, 0.f};
#pragma unroll
    for (int jr = 0; jr < 4; jr++) {
        float y0 = acc[jr][0] + bcol[0];
        float y1 = acc[jr][1] + bcol[1];
        float y2 = acc[jr][2] + bcol[2];
        float y3 = acc[jr][3] + bcol[3];
        ls[0] += y0; ls[1] += y1; ls[2] += y2; ls[3] += y3;
        lq[0] += y0 * y0; lq[1] += y1 * y1; lq[2] += y2 * y2; lq[3] += y3 * y3;
        int r = row0 + ty * 4 + jr;
        *reinterpret_cast<float4*>(&Y[(size_t)r * D + tx * 4]) =
            make_float4(y0, y1, y2, y3);
    }

    float* rs = &sA[0][0];
    float* rq = rs + 1024;
#pragma unroll
    for (int j = 0; j < 4; j++) {
        rs[ty * 64 + tx * 4 + j] = ls[j];
        rq[ty * 64 + tx * 4 + j] = lq[j];
    }
    __syncthreads();
    if (t < 64) {
        float s = 0.f, q = 0.f;
#pragma unroll
        for (int g = 0; g < 16; g++) {
            s += rs[g * 64 + t];
            q += rq[g * 64 + t];
        }
        atomicAdd(&st[t], s);
        atomicAdd(&st[64 + t], q);
    }
}

// ------------------------- BN finalize --------------------------------------
__global__ void k_finalize(const float* __restrict__ st,
                           const float* __restrict__ gamma, const float* __restrict__ beta,
                           float inv, float* __restrict__ scale, float* __restrict__ shift) {
    int t = threadIdx.x;
    float mean = st[t] * inv;
    float var  = st[64 + t] * inv - mean * mean;
    float is   = rsqrtf(var + 1e-5f);
    float sc   = gamma[t] * is;
    scale[t] = sc;
    shift[t] = beta[t] - mean * sc;
}

// ---- add2 = y2*scale_s + shift_s + shift  (full additive part of combine) --
__global__ void k_add2() {
    int idx = blockIdx.x * blockDim.x + threadIdx.x;   // < NN*D = 32768
    int c = idx & 63;
    g_add2[idx] = g_y2[idx] * g_scale_s[c] + g_shift_s[c] + g_shift[c];
}

// ------- combine + xsum fused: h = relu(Y*scale + add2[n]); xsum += h/512 ---
__global__ void __launch_bounds__(64)
k_combine_xsum(const float* __restrict__ Y, float* __restrict__ h) {
    int n  = blockIdx.x & (NN - 1);
    int sg = blockIdx.x >> 9;
    int c  = threadIdx.x;
    float scl = g_scale[c];
    float a2  = g_add2[n * D + c];
    float s0 = 0.f, s1 = 0.f;
#pragma unroll 4
    for (int j = 0; j < 64; j += 2) {
        size_t i0 = ((size_t)(sg * 64 + j)     * NN + n) * D + c;
        size_t i1 = ((size_t)(sg * 64 + j + 1) * NN + n) * D + c;
        float v0 = fmaxf(Y[i0] * scl + a2, 0.f);
        float v1 = fmaxf(Y[i1] * scl + a2, 0.f);
        h[i0] = v0; h[i1] = v1;
        s0 += v0; s1 += v1;
    }
    atomicAdd(&g_xsum[n * D + c], (s0 + s1) * (1.0f / 512.0f));
}

// ------------------------- subgraph mean of raw x (layer 0 only) -----------
__global__ void k_xsum_partial(const float* __restrict__ Y) {
    int n  = blockIdx.x & (NN - 1);
    int sg = blockIdx.x >> 9;
    int c  = threadIdx.x;
    float a0 = 0.f, a1 = 0.f;
#pragma unroll 4
    for (int j = 0; j < 64; j += 2) {
        int s = sg * 64 + j;
        a0 += Y[((size_t)(s + 0) * NN + n) * D + c];
        a1 += Y[((size_t)(s + 1) * NN + n) * D + c];
    }
    atomicAdd(&g_xsum[n * D + c], (a0 + a1) * (1.0f / 512.0f));
}

// ------------------------- small graph scatter ------------------------------
__global__ void k_scatter_s(const int* __restrict__ src, const int* __restrict__ dst) {
    int t = blockIdx.x * blockDim.x + threadIdx.x;
    int e = t >> 6, c = t & 63;
    if (e < EO) atomicAdd(&g_aggs[dst[e] * D + c], g_xsum[src[e] * D + c]);
}

// ------------------------- final head: log_softmax + MLP -------------------
__global__ void k_final(const float* __restrict__ W1, const float* __restrict__ b1,
                        const float* __restrict__ W2, const float* __restrict__ b2,
                        float* __restrict__ out) {
    __shared__ float z[64];
    __shared__ float hid[128];
    __shared__ float red[2];
    int n = blockIdx.x, t = threadIdx.x;
    if (t < 64) z[t] = g_xsum[n * D + t];
    __syncthreads();
    if (t == 0) {
        float m = -1e30f;
        for (int k = 0; k < 64; k++) m = fmaxf(m, z[k]);
        float se = 0.f;
        for (int k = 0; k < 64; k++) se += expf(z[k] - m);
        red[0] = m;
        red[1] = logf(se);
    }
    __syncthreads();
    float m = red[0], ls = red[1];
    float acc = b1[t];
    for (int k = 0; k < 64; k++) acc += (z[k] - m - ls) * W1[t * 64 + k];
    hid[t] = fmaxf(acc, 0.f);
    __syncthreads();
    if (t < 10) {
        float o = b2[t];
        for (int k = 0; k < 128; k++) o += hid[k] * W2[t * 128 + k];
        out[n * 10 + t] = o;
    }
}

// ------------------------- launcher -----------------------------------------
extern "C" void kernel_launch(void* const* d_in, const int* in_sizes, int n_in,
                              void* d_out, int out_size) {
    const float* x      = (const float*)d_in[0];
    const float* Wrel   = (const float*)d_in[1];
    const float* brel   = (const float*)d_in[2];
    const float* Wroot  = (const float*)d_in[3];
    const float* bng    = (const float*)d_in[4];
    const float* bnb    = (const float*)d_in[5];
    const float* Wrel_s = (const float*)d_in[6];
    const float* brel_s = (const float*)d_in[7];
    const float* Wroot_s= (const float*)d_in[8];
    const float* bnsg   = (const float*)d_in[9];
    const float* bnsb   = (const float*)d_in[10];
    const float* W1     = (const float*)d_in[11];
    const float* b1     = (const float*)d_in[12];
    const float* W2     = (const float*)d_in[13];
    const float* b2     = (const float*)d_in[14];
    const int*   ei     = (const int*)d_in[15];
    const int*   oe     = (const int*)d_in[16];
    float*       out    = (float*)d_out;

    cudaFuncSetAttribute(k_gemm_mma,
                         cudaFuncAttributeMaxDynamicSharedMemorySize, SM_MMA_BYTES);

    void *p_cnt, *p_hA, *p_hB, *p_Y, *p_xsum, *p_aggs, *p_y2;
    void *p_stA, *p_stS, *p_scale, *p_shift, *p_scale_s, *p_shift_s;
    cudaGetSymbolAddress(&p_cnt, g_cnt);
    cudaGetSymbolAddress(&p_hA, g_hA);
    cudaGetSymbolAddress(&p_hB, g_hB);
    cudaGetSymbolAddress(&p_Y, g_Y);
    cudaGetSymbolAddress(&p_xsum, g_xsum);
    cudaGetSymbolAddress(&p_aggs, g_aggs);
    cudaGetSymbolAddress(&p_y2, g_y2);
    cudaGetSymbolAddress(&p_stA, g_stA);
    cudaGetSymbolAddress(&p_stS, g_stS);
    cudaGetSymbolAddress(&p_scale, g_scale);
    cudaGetSymbolAddress(&p_shift, g_shift);
    cudaGetSymbolAddress(&p_scale_s, g_scale_s);
    cudaGetSymbolAddress(&p_shift_s, g_shift_s);

    // ---- CSR build ----
    cudaMemsetAsync(p_cnt, 0, NT * sizeof(int));
    k_hist<<<E_SUB / 256, 256>>>(ei + E_SUB);
    k_bsum<<<256, 256>>>();
    k_scanb<<<1, 256>>>();
    k_scanlocal<<<256, 256>>>();
    k_scatter<<<E_SUB / 256, 256>>>(ei, ei + E_SUB);

    // xsum of raw x (layer 0's subgraph input)
    cudaMemsetAsync(p_xsum, 0, NN * D * sizeof(float));
    k_xsum_partial<<<NN * 8, 64>>>(x);

    const float* hsrc = x;
    float* bufs[2] = { (float*)p_hA, (float*)p_hB };

    for (int i = 0; i < LAYERS; i++) {
        float* hdst = bufs[i & 1];

        // fused gather + big dual GEMM on tensor cores, fused BN stats
        cudaMemsetAsync(p_stA, 0, 2 * D * sizeof(float));
        k_gemm_mma<<<NT / 128, 256, SM_MMA_BYTES>>>(hsrc,
                                  Wrel + i * 4096, Wroot + i * 4096, brel + i * 64,
                                  (float*)p_Y, (float*)p_stA);

        // subgraph-level path (uses xsum of hsrc, already available)
        cudaMemsetAsync(p_aggs, 0, NN * D * sizeof(float));
        k_scatter_s<<<(EO * 64) / 256, 256>>>(oe, oe + EO);
        cudaMemsetAsync(p_stS, 0, 2 * D * sizeof(float));
        k_gemmR<<<NN / 64, 256>>>((const float*)p_aggs, (const float*)p_xsum,
                                  Wrel_s + i * 4096, Wroot_s + i * 4096, brel_s + i * 64,
                                  (float*)p_y2, (float*)p_stS);

        // finalize both BNs, build add2
        k_finalize<<<1, 64>>>((const float*)p_stA, bng + i * 64, bnb + i * 64,
                              1.0f / (float)NT, (float*)p_scale, (float*)p_shift);
        k_finalize<<<1, 64>>>((const float*)p_stS, bnsg + i * 64, bnsb + i * 64,
                              1.0f / (float)NN, (float*)p_scale_s, (float*)p_shift_s);
        k_add2<<<NN * D / 256, 256>>>();

        // combine -> h_{i+1}, fused xsum(h_{i+1})
        cudaMemsetAsync(p_xsum, 0, NN * D * sizeof(float));
        k_combine_xsum<<<NN * 8, 64>>>((const float*)p_Y, hdst);

        hsrc = hdst;
    }

    // readout: xsum already holds mean of final h
    k_final<<<NN, 128>>>(W1, b1, W2, b2, out);
}

// round 12
// speedup vs baseline: 1.0758x; 1.0758x over previous
#include <cuda_runtime.h>
#include <cuda_bf16.h>
#include <cstdint>
#include <math.h>

#define NT      262144      // total nodes (512 subgraphs x 512 nodes)
#define NN      512         // nodes per subgraph / original graph
#define E_SUB   2097152     // edges in union-of-subgraphs graph
#define EO      8192        // edges in original graph
#define D       64          // emb dim
#define LAYERS  4

// ---- mma tile smem layout (word == uint32 == 2 bf16) ----
#define AP      36                      // word pitch for A rows (conflict-free)
#define AW_WORDS (128 * AP)             // 4608 words per A sub-tile
#define WW_WORDS (64 * AP)              // 2304 words per W sub-tile
#define SMO_BIAS ((4 * AW_WORDS + 4 * WW_WORDS) * 4)   // 110592
#define SM_MMA_BYTES (SMO_BIAS + 256)                  // 110848

// ------------------------- device scratch (no cudaMalloc allowed) ----------
__device__ __align__(16) float g_hA[(size_t)NT * D];
__device__ __align__(16) float g_hB[(size_t)NT * D];
__device__ __align__(16) float g_Y[(size_t)NT * D];
__device__ __align__(16) float g_agg[(size_t)NT * D];

__device__ __align__(16) float g_xsum[NN * D];
__device__ __align__(16) float g_aggs[NN * D];
__device__ __align__(16) float g_y2[NN * D];
__device__ __align__(16) float g_add2[NN * D];   // y2*scale_s + shift_s + shift

__device__ __align__(16) float g_stA[2 * D];
__device__ __align__(16) float g_stS[2 * D];
__device__ __align__(16) float g_scale[D],  g_shift[D];
__device__ __align__(16) float g_scale_s[D], g_shift_s[D];

__device__ int g_cnt[NT];
__device__ int g_rowptr[NT + 1];
__device__ int g_bsum[256];
__device__ int g_csrsrc[E_SUB];

// ------------------------- CSR build ---------------------------------------
__global__ void k_hist(const int* __restrict__ dst) {
    int e = blockIdx.x * blockDim.x + threadIdx.x;
    if (e < E_SUB) atomicAdd(&g_cnt[dst[e]], 1);
}

__global__ void k_bsum() {
    __shared__ int sh[256];
    int b = blockIdx.x, t = threadIdx.x;
    int base = b * 1024 + t * 4;
    int v = g_cnt[base] + g_cnt[base + 1] + g_cnt[base + 2] + g_cnt[base + 3];
    sh[t] = v;
    __syncthreads();
    for (int off = 128; off > 0; off >>= 1) {
        if (t < off) sh[t] += sh[t + off];
        __syncthreads();
    }
    if (t == 0) g_bsum[b] = sh[0];
}

__global__ void k_scanb() {
    __shared__ int sh[256];
    int t = threadIdx.x;
    int orig = g_bsum[t];
    sh[t] = orig;
    __syncthreads();
    for (int off = 1; off < 256; off <<= 1) {
        int v = (t >= off) ? sh[t - off] : 0;
        __syncthreads();
        sh[t] += v;
        __syncthreads();
    }
    g_bsum[t] = sh[t] - orig;   // exclusive
}

__global__ void k_scanlocal() {
    __shared__ int sh[256];
    int b = blockIdx.x, t = threadIdx.x;
    int base = (b * 256 + t) * 4;
    int c0 = g_cnt[base], c1 = g_cnt[base + 1], c2 = g_cnt[base + 2], c3 = g_cnt[base + 3];
    int tsum = c0 + c1 + c2 + c3;
    sh[t] = tsum;
    __syncthreads();
    for (int off = 1; off < 256; off <<= 1) {
        int v = (t >= off) ? sh[t - off] : 0;
        __syncthreads();
        sh[t] += v;
        __syncthreads();
    }
    int excl = sh[t] - tsum + g_bsum[b];
    int e0 = excl, e1 = e0 + c0, e2 = e1 + c1, e3 = e2 + c2;
    g_rowptr[base] = e0; g_rowptr[base + 1] = e1;
    g_rowptr[base + 2] = e2; g_rowptr[base + 3] = e3;
    g_cnt[base] = e0; g_cnt[base + 1] = e1;
    g_cnt[base + 2] = e2; g_cnt[base + 3] = e3;
    if (b == 255 && t == 255) g_rowptr[NT] = E_SUB;
}

__global__ void k_scatter(const int* __restrict__ src, const int* __restrict__ dst) {
    int e = blockIdx.x * blockDim.x + threadIdx.x;
    if (e < E_SUB) {
        int pos = atomicAdd(&g_cnt[dst[e]], 1);
        g_csrsrc[pos] = src[e];
    }
}

// ------------------------- edge aggregation (atomic-free) -------------------
__global__ void k_gather(const float* __restrict__ h) {
    int gw = (blockIdx.x * blockDim.x + threadIdx.x) >> 5;
    int lane = threadIdx.x & 31;
    if (gw >= NT) return;
    int s = g_rowptr[gw], e = g_rowptr[gw + 1];
    const float2* h2 = reinterpret_cast<const float2*>(h);
    float2 a = make_float2(0.f, 0.f), b = make_float2(0.f, 0.f);
    int i = s;
    for (; i + 1 < e; i += 2) {
        int s0 = g_csrsrc[i], s1 = g_csrsrc[i + 1];
        float2 v0 = h2[(size_t)s0 * 32 + lane];
        float2 v1 = h2[(size_t)s1 * 32 + lane];
        a.x += v0.x; a.y += v0.y;
        b.x += v1.x; b.y += v1.y;
    }
    if (i < e) {
        int s0 = g_csrsrc[i];
        float2 v0 = h2[(size_t)s0 * 32 + lane];
        a.x += v0.x; a.y += v0.y;
    }
    reinterpret_cast<float2*>(g_agg)[(size_t)gw * 32 + lane] =
        make_float2(a.x + b.x, a.y + b.y);
}

// ---------------- bf16 split helpers ----------------------------------------
__device__ __forceinline__ void split2(float x, float y, uint32_t& hi, uint32_t& lo) {
    __nv_bfloat16 hx = __float2bfloat16_rn(x);
    __nv_bfloat16 hy = __float2bfloat16_rn(y);
    __nv_bfloat162 hp = __halves2bfloat162(hx, hy);          // low half = x
    hi = *reinterpret_cast<uint32_t*>(&hp);
    __nv_bfloat162 lp = __floats2bfloat162_rn(
        x - __bfloat162float(hx), y - __bfloat162float(hy));
    lo = *reinterpret_cast<uint32_t*>(&lp);
}

__device__ __forceinline__ void mma_bf16(float* c, uint32_t a0, uint32_t a1,
                                         uint32_t a2, uint32_t a3,
                                         uint32_t b0, uint32_t b1) {
    asm volatile(
        "mma.sync.aligned.m16n8k16.row.col.f32.bf16.bf16.f32 "
        "{%0,%1,%2,%3}, {%4,%5,%6,%7}, {%8,%9}, {%0,%1,%2,%3};"
        : "+f"(c[0]), "+f"(c[1]), "+f"(c[2]), "+f"(c[3])
        : "r"(a0), "r"(a1), "r"(a2), "r"(a3), "r"(b0), "r"(b1));
}

// -------- big dual GEMM on tensor cores (mma.sync bf16 split) ---------------
// Y[r][c] = sum_k A0[r][k]*W0[c][k] + A1[r][k]*W1[c][k] + bias[c]
// per operand: D += Ah*Wh + Al*Wh + Ah*Wl   (Al*Wl dropped, ~2^-17 rel)
__global__ void __launch_bounds__(256, 2)
k_gemm_mma(const float* __restrict__ A0, const float* __restrict__ A1,
           const float* __restrict__ W0, const float* __restrict__ W1v,
           const float* __restrict__ bias, float* __restrict__ Y,
           float* __restrict__ st) {
    extern __shared__ char smem[];
    uint32_t* Aw = reinterpret_cast<uint32_t*>(smem);             // Ah0 Al0 Ah1 Al1
    uint32_t* Ww = Aw + 4 * AW_WORDS;                             // Wh0 Wl0 Wh1 Wl1
    float* bias_s = reinterpret_cast<float*>(smem + SMO_BIAS);

    int t = threadIdx.x;
    int w = t >> 5, lane = t & 31;
    int g = lane >> 2, tg = lane & 3;
    int row0 = blockIdx.x * 128;

    if (t < 64) bias_s[t] = bias[t];

    // ---- A tiles: 128x64 fp32 -> bf16 hi/lo (word layout [row][AP]) ----
    for (int p = 0; p < 2; p++) {
        const float4* src = reinterpret_cast<const float4*>(
            (p ? A1 : A0) + (size_t)row0 * D);
        uint32_t* hb = Aw + (2 * p) * AW_WORDS;
        uint32_t* lb = hb + AW_WORDS;
#pragma unroll
        for (int it = 0; it < 8; it++) {
            int task = it * 256 + t;        // 2048 tasks = 128 rows x 16 float4
            int r = task >> 4, f = task & 15;
            float4 v = src[r * 16 + f];
            uint32_t h0, l0, h1, l1;
            split2(v.x, v.y, h0, l0);
            split2(v.z, v.w, h1, l1);
            hb[r * AP + 2 * f]     = h0;
            hb[r * AP + 2 * f + 1] = h1;
            lb[r * AP + 2 * f]     = l0;
            lb[r * AP + 2 * f + 1] = l1;
        }
    }
    // ---- W tiles: 64x64 fp32 -> bf16 hi/lo ----
    for (int p = 0; p < 2; p++) {
        const float4* src = reinterpret_cast<const float4*>(p ? W1v : W0);
        uint32_t* hb = Ww + (2 * p) * WW_WORDS;
        uint32_t* lb = hb + WW_WORDS;
#pragma unroll
        for (int it = 0; it < 4; it++) {
            int task = it * 256 + t;        // 1024 tasks = 64 rows x 16 float4
            int r = task >> 4, f = task & 15;
            float4 v = src[r * 16 + f];
            uint32_t h0, l0, h1, l1;
            split2(v.x, v.y, h0, l0);
            split2(v.z, v.w, h1, l1);
            hb[r * AP + 2 * f]     = h0;
            hb[r * AP + 2 * f + 1] = h1;
            lb[r * AP + 2 * f]     = l0;
            lb[r * AP + 2 * f + 1] = l1;
        }
    }
    __syncthreads();

    // ---- warp tile: 16 rows x 64 cols; acc[j] = m16n8 fragment ----
    float acc[8][4];
#pragma unroll
    for (int j = 0; j < 8; j++)
#pragma unroll
        for (int i = 0; i < 4; i++) acc[j][i] = 0.f;

    int ra = (w * 16 + g) * AP;
    int rb = (w * 16 + g + 8) * AP;

#pragma unroll
    for (int p = 0; p < 2; p++) {
        const uint32_t* Ah_ = Aw + (2 * p) * AW_WORDS;
        const uint32_t* Al_ = Ah_ + AW_WORDS;
        const uint32_t* Wh_ = Ww + (2 * p) * WW_WORDS;
        const uint32_t* Wl_ = Wh_ + WW_WORDS;
#pragma unroll
        for (int ks = 0; ks < 4; ks++) {
            int o = ks * 8 + tg;
            uint32_t ah0 = Ah_[ra + o],     ah1 = Ah_[rb + o];
            uint32_t ah2 = Ah_[ra + o + 4], ah3 = Ah_[rb + o + 4];
            uint32_t al0 = Al_[ra + o],     al1 = Al_[rb + o];
            uint32_t al2 = Al_[ra + o + 4], al3 = Al_[rb + o + 4];
#pragma unroll
            for (int j = 0; j < 8; j++) {
                int wb = (j * 8 + g) * AP + o;
                uint32_t bh0 = Wh_[wb], bh1 = Wh_[wb + 4];
                uint32_t bl0 = Wl_[wb], bl1 = Wl_[wb + 4];
                mma_bf16(acc[j], ah0, ah1, ah2, ah3, bh0, bh1);
                mma_bf16(acc[j], al0, al1, al2, al3, bh0, bh1);
                mma_bf16(acc[j], ah0, ah1, ah2, ah3, bl0, bl1);
            }
        }
    }

    // ---- epilogue: bias, write Y, BN stat partials ----
    float ps0[8], ps1[8], pq0[8], pq1[8];
    int r0g = row0 + w * 16 + g;
#pragma unroll
    for (int j = 0; j < 8; j++) {
        int c0 = j * 8 + 2 * tg;
        float b0 = bias_s[c0], b1 = bias_s[c0 + 1];
        float y00 = acc[j][0] + b0, y01 = acc[j][1] + b1;
        float y10 = acc[j][2] + b0, y11 = acc[j][3] + b1;
        *reinterpret_cast<float2*>(&Y[(size_t)r0g * D + c0]) = make_float2(y00, y01);
        *reinterpret_cast<float2*>(&Y[(size_t)(r0g + 8) * D + c0]) = make_float2(y10, y11);
        ps0[j] = y00 + y10; ps1[j] = y01 + y11;
        pq0[j] = y00 * y00 + y10 * y10;
        pq1[j] = y01 * y01 + y11 * y11;
    }

    __syncthreads();                                  // smem A/W now free
    float* redS = reinterpret_cast<float*>(smem);     // [64][72]
    float* redQ = redS + 64 * 72;
    int grp = w * 8 + g;
#pragma unroll
    for (int j = 0; j < 8; j++) {
        int c0 = j * 8 + 2 * tg;
        *reinterpret_cast<float2*>(&redS[grp * 72 + c0]) = make_float2(ps0[j], ps1[j]);
        *reinterpret_cast<float2*>(&redQ[grp * 72 + c0]) = make_float2(pq0[j], pq1[j]);
    }
    __syncthreads();
    if (t < 64) {
        float s = 0.f, q = 0.f;
#pragma unroll 4
        for (int k = 0; k < 64; k++) {
            s += redS[k * 72 + t];
            q += redQ[k * 72 + t];
        }
        atomicAdd(&st[t], s);
        atomicAdd(&st[64 + t], q);
    }
}

// ------------------------- small dual GEMM (scalar, fused stats) ------------
__global__ void __launch_bounds__(256)
k_gemmR(const float* __restrict__ A0, const float* __restrict__ A1,
        const float* __restrict__ W0, const float* __restrict__ W1v,
        const float* __restrict__ bias, float* __restrict__ Y,
        float* __restrict__ st) {
    __shared__ __align__(16) float sA[64][65];
    __shared__ __align__(16) float sW[64][68];
    int t  = threadIdx.x;
    int tx = t & 15, ty = t >> 4;
    int row0 = blockIdx.x * 64;
    int cc = t & 63, rb = t >> 6;

    float acc[4][4];
#pragma unroll
    for (int i = 0; i < 4; i++)
#pragma unroll
        for (int j = 0; j < 4; j++) acc[i][j] = 0.f;

    for (int p = 0; p < 2; p++) {
        const float* A = p ? A1 : A0;
        const float* W = p ? W1v : W0;
#pragma unroll
        for (int j = 0; j < 16; j++) {
            int r = rb + j * 4;
            sA[cc][r] = A[(size_t)(row0 + r) * D + cc];
        }
#pragma unroll
        for (int j = 0; j < 16; j++) {
            int ci = rb + j * 4;
            sW[cc][ci] = W[ci * D + cc];
        }
        __syncthreads();
#pragma unroll
        for (int k = 0; k < 64; k++) {
            float4 bv = *reinterpret_cast<const float4*>(&sW[k][tx * 4]);
            float a0 = sA[k][ty * 4 + 0];
            float a1 = sA[k][ty * 4 + 1];
            float a2 = sA[k][ty * 4 + 2];
            float a3 = sA[k][ty * 4 + 3];
            acc[0][0] += a0 * bv.x; acc[0][1] += a0 * bv.y; acc[0][2] += a0 * bv.z; acc[0][3] += a0 * bv.w;
            acc[1][0] += a1 * bv.x; acc[1][1] += a1 * bv.y; acc[1][2] += a1 * bv.z; acc[1][3] += a1 * bv.w;
            acc[2][0] += a2 * bv.x; acc[2][1] += a2 * bv.y; acc[2][2] += a2 * bv.z; acc[2][3] += a2 * bv.w;
            acc[3][0] += a3 * bv.x; acc[3][1] += a3 * bv.y; acc[3][2] += a3 * bv.z; acc[3][3] += a3 * bv.w;
        }
        __syncthreads();
    }

    float4 bb = *reinterpret_cast<const float4*>(&bias[tx * 4]);
    float bcol[4] = { bb.x, bb.y, bb.z, bb.w };
    float ls[4] = {0.f, 0.f, 0.f, 0.f};
    float lq[4] = {0.f, 0.f, 0.f, 0.f};
#pragma unroll
    for (int jr = 0; jr < 4; jr++) {
        float y0 = acc[jr][0] + bcol[0];
        float y1 = acc[jr][1] + bcol[1];
        float y2 = acc[jr][2] + bcol[2];
        float y3 = acc[jr][3] + bcol[3];
        ls[0] += y0; ls[1] += y1; ls[2] += y2; ls[3] += y3;
        lq[0] += y0 * y0; lq[1] += y1 * y1; lq[2] += y2 * y2; lq[3] += y3 * y3;
        int r = row0 + ty * 4 + jr;
        *reinterpret_cast<float4*>(&Y[(size_t)r * D + tx * 4]) =
            make_float4(y0, y1, y2, y3);
    }

    float* rs = &sA[0][0];
    float* rq = rs + 1024;
#pragma unroll
    for (int j = 0; j < 4; j++) {
        rs[ty * 64 + tx * 4 + j] = ls[j];
        rq[ty * 64 + tx * 4 + j] = lq[j];
    }
    __syncthreads();
    if (t < 64) {
        float s = 0.f, q = 0.f;
#pragma unroll
        for (int g = 0; g < 16; g++) {
            s += rs[g * 64 + t];
            q += rq[g * 64 + t];
        }
        atomicAdd(&st[t], s);
        atomicAdd(&st[64 + t], q);
    }
}

// ---- post: finalize both BNs, build add2, zero next-layer accumulators -----
__global__ void __launch_bounds__(256)
k_post(const float* __restrict__ bng, const float* __restrict__ bnb,
       const float* __restrict__ bnsg, const float* __restrict__ bnsb) {
    int t = threadIdx.x;
    if (t < 64) {
        float mean = g_stA[t] * (1.0f / (float)NT);
        float var  = g_stA[64 + t] * (1.0f / (float)NT) - mean * mean;
        float sc   = bng[t] * rsqrtf(var + 1e-5f);
        g_scale[t] = sc;
        g_shift[t] = bnb[t] - mean * sc;

        float mean_s = g_stS[t] * (1.0f / (float)NN);
        float var_s  = g_stS[64 + t] * (1.0f / (float)NN) - mean_s * mean_s;
        float sc_s   = bnsg[t] * rsqrtf(var_s + 1e-5f);
        g_scale_s[t] = sc_s;
        g_shift_s[t] = bnsb[t] - mean_s * sc_s;
    }
    __syncthreads();
    // add2 + zero xsum/aggs (consumed already this layer; reset for next)
    for (int idx = t; idx < NN * D; idx += 256) {
        int c = idx & 63;
        g_add2[idx] = g_y2[idx] * g_scale_s[c] + g_shift_s[c] + g_shift[c];
        g_xsum[idx] = 0.f;
        g_aggs[idx] = 0.f;
    }
    if (t < 128) { g_stA[t] = 0.f; g_stS[t] = 0.f; }
}

// ------- combine + xsum fused: h = relu(Y*scale + add2[n]); xsum += h/512 ---
__global__ void __launch_bounds__(64)
k_combine_xsum(const float* __restrict__ Y, float* __restrict__ h) {
    int n  = blockIdx.x & (NN - 1);
    int sg = blockIdx.x >> 9;
    int c  = threadIdx.x;
    float scl = g_scale[c];
    float a2  = g_add2[n * D + c];
    float s0 = 0.f, s1 = 0.f;
#pragma unroll 4
    for (int j = 0; j < 64; j += 2) {
        size_t i0 = ((size_t)(sg * 64 + j)     * NN + n) * D + c;
        size_t i1 = ((size_t)(sg * 64 + j + 1) * NN + n) * D + c;
        float v0 = fmaxf(Y[i0] * scl + a2, 0.f);
        float v1 = fmaxf(Y[i1] * scl + a2, 0.f);
        h[i0] = v0; h[i1] = v1;
        s0 += v0; s1 += v1;
    }
    atomicAdd(&g_xsum[n * D + c], (s0 + s1) * (1.0f / 512.0f));
}

// ------------------------- subgraph mean of raw x (layer 0 only) -----------
__global__ void k_xsum_partial(const float* __restrict__ Y) {
    int n  = blockIdx.x & (NN - 1);
    int sg = blockIdx.x >> 9;
    int c  = threadIdx.x;
    float a0 = 0.f, a1 = 0.f;
#pragma unroll 4
    for (int j = 0; j < 64; j += 2) {
        int s = sg * 64 + j;
        a0 += Y[((size_t)(s + 0) * NN + n) * D + c];
        a1 += Y[((size_t)(s + 1) * NN + n) * D + c];
    }
    atomicAdd(&g_xsum[n * D + c], (a0 + a1) * (1.0f / 512.0f));
}

// ------------------------- small graph scatter ------------------------------
__global__ void k_scatter_s(const int* __restrict__ src, const int* __restrict__ dst) {
    int t = blockIdx.x * blockDim.x + threadIdx.x;
    int e = t >> 6, c = t & 63;
    if (e < EO) atomicAdd(&g_aggs[dst[e] * D + c], g_xsum[src[e] * D + c]);
}

// ------------------------- final head: log_softmax + MLP -------------------
__global__ void k_final(const float* __restrict__ W1, const float* __restrict__ b1,
                        const float* __restrict__ W2, const float* __restrict__ b2,
                        float* __restrict__ out) {
    __shared__ float z[64];
    __shared__ float hid[128];
    __shared__ float red[2];
    int n = blockIdx.x, t = threadIdx.x;
    if (t < 64) z[t] = g_xsum[n * D + t];
    __syncthreads();
    if (t == 0) {
        float m = -1e30f;
        for (int k = 0; k < 64; k++) m = fmaxf(m, z[k]);
        float se = 0.f;
        for (int k = 0; k < 64; k++) se += expf(z[k] - m);
        red[0] = m;
        red[1] = logf(se);
    }
    __syncthreads();
    float m = red[0], ls = red[1];
    float acc = b1[t];
    for (int k = 0; k < 64; k++) acc += (z[k] - m - ls) * W1[t * 64 + k];
    hid[t] = fmaxf(acc, 0.f);
    __syncthreads();
    if (t < 10) {
        float o = b2[t];
        for (int k = 0; k < 128; k++) o += hid[k] * W2[t * 128 + k];
        out[n * 10 + t] = o;
    }
}

// ------------------------- launcher -----------------------------------------
extern "C" void kernel_launch(void* const* d_in, const int* in_sizes, int n_in,
                              void* d_out, int out_size) {
    const float* x      = (const float*)d_in[0];
    const float* Wrel   = (const float*)d_in[1];
    const float* brel   = (const float*)d_in[2];
    const float* Wroot  = (const float*)d_in[3];
    const float* bng    = (const float*)d_in[4];
    const float* bnb    = (const float*)d_in[5];
    const float* Wrel_s = (const float*)d_in[6];
    const float* brel_s = (const float*)d_in[7];
    const float* Wroot_s= (const float*)d_in[8];
    const float* bnsg   = (const float*)d_in[9];
    const float* bnsb   = (const float*)d_in[10];
    const float* W1     = (const float*)d_in[11];
    const float* b1     = (const float*)d_in[12];
    const float* W2     = (const float*)d_in[13];
    const float* b2     = (const float*)d_in[14];
    const int*   ei     = (const int*)d_in[15];
    const int*   oe     = (const int*)d_in[16];
    float*       out    = (float*)d_out;

    cudaFuncSetAttribute(k_gemm_mma,
                         cudaFuncAttributeMaxDynamicSharedMemorySize, SM_MMA_BYTES);

    void *p_cnt, *p_hA, *p_hB, *p_Y, *p_agg, *p_xsum, *p_aggs, *p_y2;
    void *p_stA, *p_stS;
    cudaGetSymbolAddress(&p_cnt, g_cnt);
    cudaGetSymbolAddress(&p_hA, g_hA);
    cudaGetSymbolAddress(&p_hB, g_hB);
    cudaGetSymbolAddress(&p_Y, g_Y);
    cudaGetSymbolAddress(&p_agg, g_agg);
    cudaGetSymbolAddress(&p_xsum, g_xsum);
    cudaGetSymbolAddress(&p_aggs, g_aggs);
    cudaGetSymbolAddress(&p_y2, g_y2);
    cudaGetSymbolAddress(&p_stA, g_stA);
    cudaGetSymbolAddress(&p_stS, g_stS);

    // ---- CSR build ----
    cudaMemsetAsync(p_cnt, 0, NT * sizeof(int));
    k_hist<<<E_SUB / 256, 256>>>(ei + E_SUB);
    k_bsum<<<256, 256>>>();
    k_scanb<<<1, 256>>>();
    k_scanlocal<<<256, 256>>>();
    k_scatter<<<E_SUB / 256, 256>>>(ei, ei + E_SUB);

    // ---- one-time zero of accumulators + xsum of raw x ----
    cudaMemsetAsync(p_xsum, 0, NN * D * sizeof(float));
    cudaMemsetAsync(p_aggs, 0, NN * D * sizeof(float));
    cudaMemsetAsync(p_stA, 0, 2 * D * sizeof(float));
    cudaMemsetAsync(p_stS, 0, 2 * D * sizeof(float));
    k_xsum_partial<<<NN * 8, 64>>>(x);

    const float* hsrc = x;
    float* bufs[2] = { (float*)p_hA, (float*)p_hB };

    for (int i = 0; i < LAYERS; i++) {
        float* hdst = bufs[i & 1];

        // edge aggregation over materialized h
        k_gather<<<(NT * 32) / 256, 256>>>(hsrc);

        // big dual GEMM on tensor cores (mma.sync bf16 split), fused BN stats
        k_gemm_mma<<<NT / 128, 256, SM_MMA_BYTES>>>((const float*)p_agg, hsrc,
                                  Wrel + i * 4096, Wroot + i * 4096, brel + i * 64,
                                  (float*)p_Y, (float*)p_stA);

        // subgraph-level path (uses xsum of hsrc, already available)
        k_scatter_s<<<(EO * 64) / 256, 256>>>(oe, oe + EO);
        k_gemmR<<<NN / 64, 256>>>((const float*)p_aggs, (const float*)p_xsum,
                                  Wrel_s + i * 4096, Wroot_s + i * 4096, brel_s + i * 64,
                                  (float*)p_y2, (float*)p_stS);

        // finalize BNs + add2 + zero accumulators for next layer
        k_post<<<1, 256>>>(bng + i * 64, bnb + i * 64, bnsg + i * 64, bnsb + i * 64);

        // combine -> h_{i+1}, fused xsum(h_{i+1})
        k_combine_xsum<<<NN * 8, 64>>>((const float*)p_Y, hdst);

        hsrc = hdst;
    }

    // readout: xsum already holds mean of final h
    k_final<<<NN, 128>>>(W1, b1, W2, b2, out);
}

// round 13
// speedup vs baseline: 1.2307x; 1.1440x over previous
#include <cuda_runtime.h>
#include <cuda_bf16.h>
#include <cstdint>
#include <math.h>

#define NT      262144      // total nodes (512 subgraphs x 512 nodes)
#define NN      512         // nodes per subgraph / original graph
#define E_SUB   2097152     // edges in union-of-subgraphs graph
#define EO      8192        // edges in original graph
#define D       64          // emb dim
#define LAYERS  4

// ---- mma tile smem layout (word == uint32 == 2 bf16) ----
#define AP      36                      // word pitch for A rows (conflict-free)
#define AW_WORDS (128 * AP)             // 4608 words per A sub-tile
#define WW_WORDS (64 * AP)              // 2304 words per W sub-tile
#define SMO_BIAS ((4 * AW_WORDS + 4 * WW_WORDS) * 4)   // 110592
#define SM_MMA_BYTES (SMO_BIAS + 256)                  // 110848

// ------------------------- device scratch (no cudaMalloc allowed) ----------
__device__ __align__(16) float g_hA[(size_t)NT * D];
__device__ __align__(16) float g_hB[(size_t)NT * D];
__device__ __align__(16) float g_Y[(size_t)NT * D];
__device__ __align__(16) float g_agg[(size_t)NT * D];

__device__ __align__(16) float g_xsum[NN * D];
__device__ __align__(16) float g_aggs[NN * D];
__device__ __align__(16) float g_y2[NN * D];
__device__ __align__(16) float g_add2[NN * D];   // y2*scale_s + shift_s + shift

__device__ __align__(16) float g_stA[2 * D];
__device__ __align__(16) float g_stS[2 * D];
__device__ __align__(16) float g_scale[D],  g_shift[D];
__device__ __align__(16) float g_scale_s[D], g_shift_s[D];

__device__ int g_cnt[NT];
__device__ int g_rowptr[NT + 1];
__device__ int g_bsum[256];
__device__ int g_csrsrc[E_SUB];

// ------------------------- CSR build ---------------------------------------
__global__ void k_hist(const int* __restrict__ dst) {
    int e = blockIdx.x * blockDim.x + threadIdx.x;
    if (e < E_SUB) atomicAdd(&g_cnt[dst[e]], 1);
}

__global__ void k_bsum() {
    __shared__ int sh[256];
    int b = blockIdx.x, t = threadIdx.x;
    int base = b * 1024 + t * 4;
    int v = g_cnt[base] + g_cnt[base + 1] + g_cnt[base + 2] + g_cnt[base + 3];
    sh[t] = v;
    __syncthreads();
    for (int off = 128; off > 0; off >>= 1) {
        if (t < off) sh[t] += sh[t + off];
        __syncthreads();
    }
    if (t == 0) g_bsum[b] = sh[0];
}

__global__ void k_scanb() {
    __shared__ int sh[256];
    int t = threadIdx.x;
    int orig = g_bsum[t];
    sh[t] = orig;
    __syncthreads();
    for (int off = 1; off < 256; off <<= 1) {
        int v = (t >= off) ? sh[t - off] : 0;
        __syncthreads();
        sh[t] += v;
        __syncthreads();
    }
    g_bsum[t] = sh[t] - orig;   // exclusive
}

__global__ void k_scanlocal() {
    __shared__ int sh[256];
    int b = blockIdx.x, t = threadIdx.x;
    int base = (b * 256 + t) * 4;
    int c0 = g_cnt[base], c1 = g_cnt[base + 1], c2 = g_cnt[base + 2], c3 = g_cnt[base + 3];
    int tsum = c0 + c1 + c2 + c3;
    sh[t] = tsum;
    __syncthreads();
    for (int off = 1; off < 256; off <<= 1) {
        int v = (t >= off) ? sh[t - off] : 0;
        __syncthreads();
        sh[t] += v;
        __syncthreads();
    }
    int excl = sh[t] - tsum + g_bsum[b];
    int e0 = excl, e1 = e0 + c0, e2 = e1 + c1, e3 = e2 + c2;
    g_rowptr[base] = e0; g_rowptr[base + 1] = e1;
    g_rowptr[base + 2] = e2; g_rowptr[base + 3] = e3;
    g_cnt[base] = e0; g_cnt[base + 1] = e1;
    g_cnt[base + 2] = e2; g_cnt[base + 3] = e3;
    if (b == 255 && t == 255) g_rowptr[NT] = E_SUB;
}

__global__ void k_scatter(const int* __restrict__ src, const int* __restrict__ dst) {
    int e = blockIdx.x * blockDim.x + threadIdx.x;
    if (e < E_SUB) {
        int pos = atomicAdd(&g_cnt[dst[e]], 1);
        g_csrsrc[pos] = src[e];
    }
}

// ------------------------- edge aggregation (atomic-free) -------------------
__global__ void k_gather(const float* __restrict__ h) {
    int gw = (blockIdx.x * blockDim.x + threadIdx.x) >> 5;
    int lane = threadIdx.x & 31;
    if (gw >= NT) return;
    int s = g_rowptr[gw], e = g_rowptr[gw + 1];
    const float2* h2 = reinterpret_cast<const float2*>(h);
    float2 a = make_float2(0.f, 0.f), b = make_float2(0.f, 0.f);
    int i = s;
    for (; i + 1 < e; i += 2) {
        int s0 = g_csrsrc[i], s1 = g_csrsrc[i + 1];
        float2 v0 = h2[(size_t)s0 * 32 + lane];
        float2 v1 = h2[(size_t)s1 * 32 + lane];
        a.x += v0.x; a.y += v0.y;
        b.x += v1.x; b.y += v1.y;
    }
    if (i < e) {
        int s0 = g_csrsrc[i];
        float2 v0 = h2[(size_t)s0 * 32 + lane];
        a.x += v0.x; a.y += v0.y;
    }
    reinterpret_cast<float2*>(g_agg)[(size_t)gw * 32 + lane] =
        make_float2(a.x + b.x, a.y + b.y);
}

// ---------------- bf16 split helpers ----------------------------------------
__device__ __forceinline__ void split2(float x, float y, uint32_t& hi, uint32_t& lo) {
    __nv_bfloat16 hx = __float2bfloat16_rn(x);
    __nv_bfloat16 hy = __float2bfloat16_rn(y);
    __nv_bfloat162 hp = __halves2bfloat162(hx, hy);          // low half = x
    hi = *reinterpret_cast<uint32_t*>(&hp);
    __nv_bfloat162 lp = __floats2bfloat162_rn(
        x - __bfloat162float(hx), y - __bfloat162float(hy));
    lo = *reinterpret_cast<uint32_t*>(&lp);
}

__device__ __forceinline__ void mma_bf16(float* c, uint32_t a0, uint32_t a1,
                                         uint32_t a2, uint32_t a3,
                                         uint32_t b0, uint32_t b1) {
    asm volatile(
        "mma.sync.aligned.m16n8k16.row.col.f32.bf16.bf16.f32 "
        "{%0,%1,%2,%3}, {%4,%5,%6,%7}, {%8,%9}, {%0,%1,%2,%3};"
        : "+f"(c[0]), "+f"(c[1]), "+f"(c[2]), "+f"(c[3])
        : "r"(a0), "r"(a1), "r"(a2), "r"(a3), "r"(b0), "r"(b1));
}

// -------- big dual GEMM on tensor cores (mma.sync bf16 split) ---------------
// Y[r][c] = sum_k A0[r][k]*W0[c][k] + A1[r][k]*W1[c][k] + bias[c]
// per operand: D += Ah*Wh + Al*Wh + Ah*Wl   (Al*Wl dropped, ~2^-17 rel)
__global__ void __launch_bounds__(256, 2)
k_gemm_mma(const float* __restrict__ A0, const float* __restrict__ A1,
           const float* __restrict__ W0, const float* __restrict__ W1v,
           const float* __restrict__ bias, float* __restrict__ Y,
           float* __restrict__ st) {
    extern __shared__ char smem[];
    uint32_t* Aw = reinterpret_cast<uint32_t*>(smem);             // Ah0 Al0 Ah1 Al1
    uint32_t* Ww = Aw + 4 * AW_WORDS;                             // Wh0 Wl0 Wh1 Wl1
    float* bias_s = reinterpret_cast<float*>(smem + SMO_BIAS);

    int t = threadIdx.x;
    int w = t >> 5, lane = t & 31;
    int g = lane >> 2, tg = lane & 3;
    int row0 = blockIdx.x * 128;

    if (t < 64) bias_s[t] = bias[t];

    // ---- A tiles: 128x64 fp32 -> bf16 hi/lo (word layout [row][AP]) ----
    for (int p = 0; p < 2; p++) {
        const float4* src = reinterpret_cast<const float4*>(
            (p ? A1 : A0) + (size_t)row0 * D);
        uint32_t* hb = Aw + (2 * p) * AW_WORDS;
        uint32_t* lb = hb + AW_WORDS;
#pragma unroll
        for (int it = 0; it < 8; it++) {
            int task = it * 256 + t;        // 2048 tasks = 128 rows x 16 float4
            int r = task >> 4, f = task & 15;
            float4 v = src[r * 16 + f];
            uint32_t h0, l0, h1, l1;
            split2(v.x, v.y, h0, l0);
            split2(v.z, v.w, h1, l1);
            hb[r * AP + 2 * f]     = h0;
            hb[r * AP + 2 * f + 1] = h1;
            lb[r * AP + 2 * f]     = l0;
            lb[r * AP + 2 * f + 1] = l1;
        }
    }
    // ---- W tiles: 64x64 fp32 -> bf16 hi/lo ----
    for (int p = 0; p < 2; p++) {
        const float4* src = reinterpret_cast<const float4*>(p ? W1v : W0);
        uint32_t* hb = Ww + (2 * p) * WW_WORDS;
        uint32_t* lb = hb + WW_WORDS;
#pragma unroll
        for (int it = 0; it < 4; it++) {
            int task = it * 256 + t;        // 1024 tasks = 64 rows x 16 float4
            int r = task >> 4, f = task & 15;
            float4 v = src[r * 16 + f];
            uint32_t h0, l0, h1, l1;
            split2(v.x, v.y, h0, l0);
            split2(v.z, v.w, h1, l1);
            hb[r * AP + 2 * f]     = h0;
            hb[r * AP + 2 * f + 1] = h1;
            lb[r * AP + 2 * f]     = l0;
            lb[r * AP + 2 * f + 1] = l1;
        }
    }
    __syncthreads();

    // ---- warp tile: 16 rows x 64 cols; acc[j] = m16n8 fragment ----
    float acc[8][4];
#pragma unroll
    for (int j = 0; j < 8; j++)
#pragma unroll
        for (int i = 0; i < 4; i++) acc[j][i] = 0.f;

    int ra = (w * 16 + g) * AP;
    int rb = (w * 16 + g + 8) * AP;

#pragma unroll
    for (int p = 0; p < 2; p++) {
        const uint32_t* Ah_ = Aw + (2 * p) * AW_WORDS;
        const uint32_t* Al_ = Ah_ + AW_WORDS;
        const uint32_t* Wh_ = Ww + (2 * p) * WW_WORDS;
        const uint32_t* Wl_ = Wh_ + WW_WORDS;
#pragma unroll
        for (int ks = 0; ks < 4; ks++) {
            int o = ks * 8 + tg;
            uint32_t ah0 = Ah_[ra + o],     ah1 = Ah_[rb + o];
            uint32_t ah2 = Ah_[ra + o + 4], ah3 = Ah_[rb + o + 4];
            uint32_t al0 = Al_[ra + o],     al1 = Al_[rb + o];
            uint32_t al2 = Al_[ra + o + 4], al3 = Al_[rb + o + 4];
#pragma unroll
            for (int j = 0; j < 8; j++) {
                int wb = (j * 8 + g) * AP + o;
                uint32_t bh0 = Wh_[wb], bh1 = Wh_[wb + 4];
                uint32_t bl0 = Wl_[wb], bl1 = Wl_[wb + 4];
                mma_bf16(acc[j], ah0, ah1, ah2, ah3, bh0, bh1);
                mma_bf16(acc[j], al0, al1, al2, al3, bh0, bh1);
                mma_bf16(acc[j], ah0, ah1, ah2, ah3, bl0, bl1);
            }
        }
    }

    // ---- epilogue: bias, write Y, BN stat partials ----
    float ps0[8], ps1[8], pq0[8], pq1[8];
    int r0g = row0 + w * 16 + g;
#pragma unroll
    for (int j = 0; j < 8; j++) {
        int c0 = j * 8 + 2 * tg;
        float b0 = bias_s[c0], b1 = bias_s[c0 + 1];
        float y00 = acc[j][0] + b0, y01 = acc[j][1] + b1;
        float y10 = acc[j][2] + b0, y11 = acc[j][3] + b1;
        *reinterpret_cast<float2*>(&Y[(size_t)r0g * D + c0]) = make_float2(y00, y01);
        *reinterpret_cast<float2*>(&Y[(size_t)(r0g + 8) * D + c0]) = make_float2(y10, y11);
        ps0[j] = y00 + y10; ps1[j] = y01 + y11;
        pq0[j] = y00 * y00 + y10 * y10;
        pq1[j] = y01 * y01 + y11 * y11;
    }

    __syncthreads();                                  // smem A/W now free
    float* redS = reinterpret_cast<float*>(smem);     // [64][72]
    float* redQ = redS + 64 * 72;
    int grp = w * 8 + g;
#pragma unroll
    for (int j = 0; j < 8; j++) {
        int c0 = j * 8 + 2 * tg;
        *reinterpret_cast<float2*>(&redS[grp * 72 + c0]) = make_float2(ps0[j], ps1[j]);
        *reinterpret_cast<float2*>(&redQ[grp * 72 + c0]) = make_float2(pq0[j], pq1[j]);
    }
    __syncthreads();
    if (t < 64) {
        float s = 0.f, q = 0.f;
#pragma unroll 4
        for (int k = 0; k < 64; k++) {
            s += redS[k * 72 + t];
            q += redQ[k * 72 + t];
        }
        atomicAdd(&st[t], s);
        atomicAdd(&st[64 + t], q);
    }
}

// ------------------------- small dual GEMM (scalar, fused stats) ------------
__global__ void __launch_bounds__(256)
k_gemmR(const float* __restrict__ A0, const float* __restrict__ A1,
        const float* __restrict__ W0, const float* __restrict__ W1v,
        const float* __restrict__ bias, float* __restrict__ Y,
        float* __restrict__ st) {
    __shared__ __align__(16) float sA[64][65];
    __shared__ __align__(16) float sW[64][68];
    int t  = threadIdx.x;
    int tx = t & 15, ty = t >> 4;
    int row0 = blockIdx.x * 64;
    int cc = t & 63, rb = t >> 6;

    float acc[4][4];
#pragma unroll
    for (int i = 0; i < 4; i++)
#pragma unroll
        for (int j = 0; j < 4; j++) acc[i][j] = 0.f;

    for (int p = 0; p < 2; p++) {
        const float* A = p ? A1 : A0;
        const float* W = p ? W1v : W0;
#pragma unroll
        for (int j = 0; j < 16; j++) {
            int r = rb + j * 4;
            sA[cc][r] = A[(size_t)(row0 + r) * D + cc];
        }
#pragma unroll
        for (int j = 0; j < 16; j++) {
            int ci = rb + j * 4;
            sW[cc][ci] = W[ci * D + cc];
        }
        __syncthreads();
#pragma unroll
        for (int k = 0; k < 64; k++) {
            float4 bv = *reinterpret_cast<const float4*>(&sW[k][tx * 4]);
            float a0 = sA[k][ty * 4 + 0];
            float a1 = sA[k][ty * 4 + 1];
            float a2 = sA[k][ty * 4 + 2];
            float a3 = sA[k][ty * 4 + 3];
            acc[0][0] += a0 * bv.x; acc[0][1] += a0 * bv.y; acc[0][2] += a0 * bv.z; acc[0][3] += a0 * bv.w;
            acc[1][0] += a1 * bv.x; acc[1][1] += a1 * bv.y; acc[1][2] += a1 * bv.z; acc[1][3] += a1 * bv.w;
            acc[2][0] += a2 * bv.x; acc[2][1] += a2 * bv.y; acc[2][2] += a2 * bv.z; acc[2][3] += a2 * bv.w;
            acc[3][0] += a3 * bv.x; acc[3][1] += a3 * bv.y; acc[3][2] += a3 * bv.z; acc[3][3] += a3 * bv.w;
        }
        __syncthreads();
    }

    float4 bb = *reinterpret_cast<const float4*>(&bias[tx * 4]);
    float bcol[4] = { bb.x, bb.y, bb.z, bb.w };
    float ls[4] = {0.f, 0.f, 0.f, 0.f};
    float lq[4] = {0.f, 0.f, 0.f, 0.f};
#pragma unroll
    for (int jr = 0; jr < 4; jr++) {
        float y0 = acc[jr][0] + bcol[0];
        float y1 = acc[jr][1] + bcol[1];
        float y2 = acc[jr][2] + bcol[2];
        float y3 = acc[jr][3] + bcol[3];
        ls[0] += y0; ls[1] += y1; ls[2] += y2; ls[3] += y3;
        lq[0] += y0 * y0; lq[1] += y1 * y1; lq[2] += y2 * y2; lq[3] += y3 * y3;
        int r = row0 + ty * 4 + jr;
        *reinterpret_cast<float4*>(&Y[(size_t)r * D + tx * 4]) =
            make_float4(y0, y1, y2, y3);
    }

    float* rs = &sA[0][0];
    float* rq = rs + 1024;
#pragma unroll
    for (int j = 0; j < 4; j++) {
        rs[ty * 64 + tx * 4 + j] = ls[j];
        rq[ty * 64 + tx * 4 + j] = lq[j];
    }
    __syncthreads();
    if (t < 64) {
        float s = 0.f, q = 0.f;
#pragma unroll
        for (int g = 0; g < 16; g++) {
            s += rs[g * 64 + t];
            q += rq[g * 64 + t];
        }
        atomicAdd(&st[t], s);
        atomicAdd(&st[64 + t], q);
    }
}

// ---- finalize both BNs (tiny: 1 KB of work) + zero stats -------------------
__global__ void k_finblock(const float* __restrict__ bng, const float* __restrict__ bnb,
                           const float* __restrict__ bnsg, const float* __restrict__ bnsb) {
    int t = threadIdx.x;   // 64 threads
    float mean = g_stA[t] * (1.0f / (float)NT);
    float var  = g_stA[64 + t] * (1.0f / (float)NT) - mean * mean;
    float sc   = bng[t] * rsqrtf(var + 1e-5f);
    g_scale[t] = sc;
    g_shift[t] = bnb[t] - mean * sc;

    float mean_s = g_stS[t] * (1.0f / (float)NN);
    float var_s  = g_stS[64 + t] * (1.0f / (float)NN) - mean_s * mean_s;
    float sc_s   = bnsg[t] * rsqrtf(var_s + 1e-5f);
    g_scale_s[t] = sc_s;
    g_shift_s[t] = bnsb[t] - mean_s * sc_s;

    g_stA[t] = 0.f; g_stA[64 + t] = 0.f;
    g_stS[t] = 0.f; g_stS[64 + t] = 0.f;
}

// ---- add2 = y2*scale_s + shift_s + shift; zero xsum/aggs (multi-block) -----
__global__ void k_add2zero() {
    int idx = blockIdx.x * blockDim.x + threadIdx.x;   // < NN*D = 32768
    int c = idx & 63;
    g_add2[idx] = g_y2[idx] * g_scale_s[c] + g_shift_s[c] + g_shift[c];
    g_xsum[idx] = 0.f;
    g_aggs[idx] = 0.f;
}

// ------- combine + xsum fused: h = relu(Y*scale + add2[n]); xsum += h/512 ---
__global__ void __launch_bounds__(64)
k_combine_xsum(const float* __restrict__ Y, float* __restrict__ h, int store_h) {
    int n  = blockIdx.x & (NN - 1);
    int sg = blockIdx.x >> 9;
    int c  = threadIdx.x;
    float scl = g_scale[c];
    float a2  = g_add2[n * D + c];
    float s0 = 0.f, s1 = 0.f;
#pragma unroll 4
    for (int j = 0; j < 64; j += 2) {
        size_t i0 = ((size_t)(sg * 64 + j)     * NN + n) * D + c;
        size_t i1 = ((size_t)(sg * 64 + j + 1) * NN + n) * D + c;
        float v0 = fmaxf(Y[i0] * scl + a2, 0.f);
        float v1 = fmaxf(Y[i1] * scl + a2, 0.f);
        if (store_h) { h[i0] = v0; h[i1] = v1; }
        s0 += v0; s1 += v1;
    }
    atomicAdd(&g_xsum[n * D + c], (s0 + s1) * (1.0f / 512.0f));
}

// ------------------------- subgraph mean of raw x (layer 0 only) -----------
__global__ void k_xsum_partial(const float* __restrict__ Y) {
    int n  = blockIdx.x & (NN - 1);
    int sg = blockIdx.x >> 9;
    int c  = threadIdx.x;
    float a0 = 0.f, a1 = 0.f;
#pragma unroll 4
    for (int j = 0; j < 64; j += 2) {
        int s = sg * 64 + j;
        a0 += Y[((size_t)(s + 0) * NN + n) * D + c];
        a1 += Y[((size_t)(s + 1) * NN + n) * D + c];
    }
    atomicAdd(&g_xsum[n * D + c], (a0 + a1) * (1.0f / 512.0f));
}

// ------------------------- small graph scatter ------------------------------
__global__ void k_scatter_s(const int* __restrict__ src, const int* __restrict__ dst) {
    int t = blockIdx.x * blockDim.x + threadIdx.x;
    int e = t >> 6, c = t & 63;
    if (e < EO) atomicAdd(&g_aggs[dst[e] * D + c], g_xsum[src[e] * D + c]);
}

// ------------------------- final head: log_softmax + MLP -------------------
__global__ void k_final(const float* __restrict__ W1, const float* __restrict__ b1,
                        const float* __restrict__ W2, const float* __restrict__ b2,
                        float* __restrict__ out) {
    __shared__ float z[64];
    __shared__ float hid[128];
    __shared__ float red[2];
    int n = blockIdx.x, t = threadIdx.x;
    if (t < 64) z[t] = g_xsum[n * D + t];
    __syncthreads();
    if (t == 0) {
        float m = -1e30f;
        for (int k = 0; k < 64; k++) m = fmaxf(m, z[k]);
        float se = 0.f;
        for (int k = 0; k < 64; k++) se += expf(z[k] - m);
        red[0] = m;
        red[1] = logf(se);
    }
    __syncthreads();
    float m = red[0], ls = red[1];
    float acc = b1[t];
    for (int k = 0; k < 64; k++) acc += (z[k] - m - ls) * W1[t * 64 + k];
    hid[t] = fmaxf(acc, 0.f);
    __syncthreads();
    if (t < 10) {
        float o = b2[t];
        for (int k = 0; k < 128; k++) o += hid[k] * W2[t * 128 + k];
        out[n * 10 + t] = o;
    }
}

// ------------------------- launcher -----------------------------------------
extern "C" void kernel_launch(void* const* d_in, const int* in_sizes, int n_in,
                              void* d_out, int out_size) {
    const float* x      = (const float*)d_in[0];
    const float* Wrel   = (const float*)d_in[1];
    const float* brel   = (const float*)d_in[2];
    const float* Wroot  = (const float*)d_in[3];
    const float* bng    = (const float*)d_in[4];
    const float* bnb    = (const float*)d_in[5];
    const float* Wrel_s = (const float*)d_in[6];
    const float* brel_s = (const float*)d_in[7];
    const float* Wroot_s= (const float*)d_in[8];
    const float* bnsg   = (const float*)d_in[9];
    const float* bnsb   = (const float*)d_in[10];
    const float* W1     = (const float*)d_in[11];
    const float* b1     = (const float*)d_in[12];
    const float* W2     = (const float*)d_in[13];
    const float* b2     = (const float*)d_in[14];
    const int*   ei     = (const int*)d_in[15];
    const int*   oe     = (const int*)d_in[16];
    float*       out    = (float*)d_out;

    cudaFuncSetAttribute(k_gemm_mma,
                         cudaFuncAttributeMaxDynamicSharedMemorySize, SM_MMA_BYTES);

    void *p_cnt, *p_hA, *p_hB, *p_Y, *p_agg, *p_xsum, *p_aggs, *p_y2;
    void *p_stA, *p_stS;
    cudaGetSymbolAddress(&p_cnt, g_cnt);
    cudaGetSymbolAddress(&p_hA, g_hA);
    cudaGetSymbolAddress(&p_hB, g_hB);
    cudaGetSymbolAddress(&p_Y, g_Y);
    cudaGetSymbolAddress(&p_agg, g_agg);
    cudaGetSymbolAddress(&p_xsum, g_xsum);
    cudaGetSymbolAddress(&p_aggs, g_aggs);
    cudaGetSymbolAddress(&p_y2, g_y2);
    cudaGetSymbolAddress(&p_stA, g_stA);
    cudaGetSymbolAddress(&p_stS, g_stS);

    // ---- CSR build ----
    cudaMemsetAsync(p_cnt, 0, NT * sizeof(int));
    k_hist<<<E_SUB / 256, 256>>>(ei + E_SUB);
    k_bsum<<<256, 256>>>();
    k_scanb<<<1, 256>>>();
    k_scanlocal<<<256, 256>>>();
    k_scatter<<<E_SUB / 256, 256>>>(ei, ei + E_SUB);

    // ---- one-time zero of accumulators + xsum of raw x ----
    cudaMemsetAsync(p_xsum, 0, NN * D * sizeof(float));
    cudaMemsetAsync(p_aggs, 0, NN * D * sizeof(float));
    cudaMemsetAsync(p_stA, 0, 2 * D * sizeof(float));
    cudaMemsetAsync(p_stS, 0, 2 * D * sizeof(float));
    k_xsum_partial<<<NN * 8, 64>>>(x);

    const float* hsrc = x;
    float* bufs[2] = { (float*)p_hA, (float*)p_hB };

    for (int i = 0; i < LAYERS; i++) {
        float* hdst = bufs[i & 1];

        // edge aggregation over materialized h
        k_gather<<<(NT * 32) / 256, 256>>>(hsrc);

        // big dual GEMM on tensor cores (mma.sync bf16 split), fused BN stats
        k_gemm_mma<<<NT / 128, 256, SM_MMA_BYTES>>>((const float*)p_agg, hsrc,
                                  Wrel + i * 4096, Wroot + i * 4096, brel + i * 64,
                                  (float*)p_Y, (float*)p_stA);

        // subgraph-level path (uses xsum of hsrc, already available)
        k_scatter_s<<<(EO * 64) / 256, 256>>>(oe, oe + EO);
        k_gemmR<<<NN / 64, 256>>>((const float*)p_aggs, (const float*)p_xsum,
                                  Wrel_s + i * 4096, Wroot_s + i * 4096, brel_s + i * 64,
                                  (float*)p_y2, (float*)p_stS);

        // finalize both BNs (tiny) then add2 + zero accumulators (parallel)
        k_finblock<<<1, 64>>>(bng + i * 64, bnb + i * 64, bnsg + i * 64, bnsb + i * 64);
        k_add2zero<<<NN * D / 256, 256>>>();

        // combine -> h_{i+1}, fused xsum(h_{i+1}); last layer: xsum only
        k_combine_xsum<<<NN * 8, 64>>>((const float*)p_Y, hdst,
                                       (i < LAYERS - 1) ? 1 : 0);

        hsrc = hdst;
    }

    // readout: xsum already holds mean of final h
    k_final<<<NN, 128>>>(W1, b1, W2, b2, out);
}